// round 17
// baseline (speedup 1.0000x reference)
#include <cuda_runtime.h>
#include <cuda_fp16.h>
#include <cstdint>
#include <cstddef>

// Problem dims
#define BB    64
#define CC    512
#define HWS   784
#define MTOT  (BB * HWS)        // 50176
#define MTILE 128
#define NTILE 256
#define KCH   64                // K chunk (fp16 -> 128B rows)
#define NCHNK (CC / KCH)        // 8

// smem: 2 stages x { A[128][128B] 16384 + B[256][128B] 32768 } = 98304
// params at 98304: 5 x 256 f32 = 5120 -> total 103424  (2 CTAs/SM)
// epilogue D half-tile 128 x 129 f32 = 66048 reuses stage area
#define ASZ      16384u
#define STAGEB   49152u
#define SMPAR    98304u
#define SMTOTAL  103424u
#define TPITCH   129

// ---------------- scratch ----------------
__device__ __half g_a[(size_t)MTOT * CC];   // binarized activations [M][K], +-1 fp16
__device__ __half g_wb[CC * CC];            // sign(W) [N][K], +-1 fp16
__device__ float g_alpha[CC];
__device__ float g_beta2[CC];

// ---------------- helpers ----------------
static __device__ __forceinline__ uint32_t smem_u32(const void* p) {
    uint32_t a;
    asm("{ .reg .u64 t; cvta.to.shared.u64 t, %1; cvt.u32.u64 %0, t; }" : "=r"(a) : "l"(p));
    return a;
}
static __device__ __forceinline__ void cp16(uint32_t s, const void* g) {
    asm volatile("cp.async.cg.shared.global [%0], [%1], 16;" :: "r"(s), "l"(g) : "memory");
}
#define CP_COMMIT() asm volatile("cp.async.commit_group;" ::: "memory")
#define CP_WAIT(n)  asm volatile("cp.async.wait_group %0;" :: "n"(n) : "memory")

static __device__ __forceinline__ void ldsm4(uint32_t* r, uint32_t a) {
    asm volatile("ldmatrix.sync.aligned.m8n8.x4.shared.b16 {%0,%1,%2,%3}, [%4];"
                 : "=r"(r[0]), "=r"(r[1]), "=r"(r[2]), "=r"(r[3]) : "r"(a));
}
static __device__ __forceinline__ void mma_h(uint32_t* c, const uint32_t* a,
                                             uint32_t b0, uint32_t b1) {
    asm volatile(
        "mma.sync.aligned.m16n8k16.row.col.f16.f16.f16.f16 "
        "{%0,%1}, {%2,%3,%4,%5}, {%6,%7}, {%0,%1};"
        : "+r"(c[0]), "+r"(c[1])
        : "r"(a[0]), "r"(a[1]), "r"(a[2]), "r"(a[3]), "r"(b0), "r"(b1));
}
static __device__ __forceinline__ uint32_t swzB(int row, int seg) {
    return (uint32_t)(row * 128 + ((seg ^ (row & 7)) << 4));
}
static __device__ __forceinline__ uint32_t sgnh2(float a, float b) {
    return ((a >= 0.f) ? 0x3C00u : 0xBC00u) | (((b >= 0.f) ? 0x3C00u : 0xBC00u) << 16);
}

// ---------------- kernel 1: prep (blocks 0..63) + binarize (blocks 64+) ----------------
__global__ void pre_kernel(const float* __restrict__ W, const float* __restrict__ gam,
                           const float* __restrict__ bet, const float* __restrict__ mea,
                           const float* __restrict__ var,
                           const float* __restrict__ x, const float* __restrict__ rb) {
    __shared__ unsigned short ts[64][72];   // binarize role only
    const int tid = threadIdx.x;

    if (blockIdx.x < 64) {
        // ---------- prep role ----------
        int wid = tid >> 5, lane = tid & 31;
        int o = blockIdx.x * 8 + wid;
        const float4* wr = reinterpret_cast<const float4*>(W + (size_t)o * CC + lane * 16);
        float s = 0.f;
        uint32_t h[8];
        #pragma unroll
        for (int j = 0; j < 4; j++) {
            float4 v = wr[j];
            s += fabsf(v.x) + fabsf(v.y) + fabsf(v.z) + fabsf(v.w);
            h[2 * j]     = sgnh2(v.x, v.y);
            h[2 * j + 1] = sgnh2(v.z, v.w);
        }
        uint4* dst = reinterpret_cast<uint4*>(g_wb + (size_t)o * CC + lane * 16);
        dst[0] = make_uint4(h[0], h[1], h[2], h[3]);
        dst[1] = make_uint4(h[4], h[5], h[6], h[7]);
        #pragma unroll
        for (int off = 16; off > 0; off >>= 1) s += __shfl_xor_sync(0xffffffffu, s, off);
        if (lane == 0) {
            float scale = s * (1.0f / 512.0f);
            float A = gam[o] * rsqrtf(var[o] + 1e-5f);
            g_alpha[o] = A * scale;
            g_beta2[o] = bet[o] - A * mea[o];
        }
        return;
    }

    // ---------- binarize role ----------
    const int bid = blockIdx.x - 64;        // 0..6655 = 13*8*64
    const int hwg = bid % 13;
    const int kg  = (bid / 13) % 8;
    const int b   = bid / 104;
    const int k0  = kg * 64;
    const int hw0 = hwg * 64;

    #pragma unroll
    for (int i = 0; i < 4; i++) {
        int idx = tid + i * 256;
        int cc = idx >> 4;
        int hs = idx & 15;
        int hw = hw0 + hs * 4;
        float rbv = rb[k0 + cc];
        const float* xp = x + (size_t)((b << 9) + k0 + cc) * HWS + hw;
        if (hw + 3 < HWS) {
            float4 v = *reinterpret_cast<const float4*>(xp);
            ts[hs * 4 + 0][cc] = (v.x + rbv >= 0.f) ? 0x3C00 : 0xBC00;
            ts[hs * 4 + 1][cc] = (v.y + rbv >= 0.f) ? 0x3C00 : 0xBC00;
            ts[hs * 4 + 2][cc] = (v.z + rbv >= 0.f) ? 0x3C00 : 0xBC00;
            ts[hs * 4 + 3][cc] = (v.w + rbv >= 0.f) ? 0x3C00 : 0xBC00;
        } else {
            #pragma unroll
            for (int e = 0; e < 4; e++)
                if (hw + e < HWS)
                    ts[hs * 4 + e][cc] = (xp[e] + rbv >= 0.f) ? 0x3C00 : 0xBC00;
        }
    }
    __syncthreads();
    #pragma unroll
    for (int i = 0; i < 2; i++) {
        int idx = tid + i * 256;
        int row = idx >> 3;
        int seg = idx & 7;
        int hw = hw0 + row;
        if (hw < HWS) {
            uint4 v = *reinterpret_cast<const uint4*>(&ts[row][seg * 8]);
            *reinterpret_cast<uint4*>(
                &g_a[(size_t)(b * HWS + hw) * CC + k0 + seg * 8]) = v;
        }
    }
}

// ---------------- kernel 2: fp16 mma GEMM (64x64 warps, B-frag double-buffer) ----------------
__global__ void __launch_bounds__(256, 2)
gemm_kernel(const float* __restrict__ x, const float* __restrict__ slope,
            const float* __restrict__ shift, const float* __restrict__ pbias,
            float* __restrict__ out)
{
    extern __shared__ char smem[];
    const uint32_t sb = smem_u32(smem);
    const int tid = threadIdx.x, wid = tid >> 5, lane = tid & 31;
    const int m0 = blockIdx.y * MTILE;
    const int n0 = blockIdx.x * NTILE;

    float* alphaS = reinterpret_cast<float*>(smem + SMPAR);
    float* betaS  = alphaS + 256;
    float* slopeS = alphaS + 512;
    float* shiftS = alphaS + 768;
    float* pbiasS = alphaS + 1024;
    alphaS[tid] = g_alpha[n0 + tid];
    betaS[tid]  = g_beta2[n0 + tid];
    slopeS[tid] = slope[n0 + tid];
    shiftS[tid] = shift[n0 + tid];
    pbiasS[tid] = pbias[n0 + tid];

    const int ldrow = tid >> 3;           // 0..31
    const int ldseg = tid & 7;
    auto load_stage = [&](int c, int st) {
        const uint32_t so = sb + (uint32_t)st * STAGEB;
        const char* ga = (const char*)g_a  + ((size_t)m0 * CC + c * KCH) * 2;
        const char* gb = (const char*)g_wb + ((size_t)n0 * CC + c * KCH) * 2;
        #pragma unroll
        for (int j = 0; j < 4; j++) {
            int row = ldrow + j * 32;
            cp16(so + swzB(row, ldseg), ga + (size_t)row * (CC * 2) + ldseg * 16);
        }
        #pragma unroll
        for (int j = 0; j < 8; j++) {
            int row = ldrow + j * 32;
            cp16(so + ASZ + swzB(row, ldseg), gb + (size_t)row * (CC * 2) + ldseg * 16);
        }
        CP_COMMIT();
    };

    load_stage(0, 0);

    uint32_t acc[4][8][2] = {};           // warp 64m x 64n, f16x2 acc
    const int mw = (wid >> 2) * 64;       // warp row: 0/64
    const int nw = (wid & 3) * 64;        // warp col: 0/64/128/192
    const int rowSel = (lane & 7) + ((lane >> 3) & 1) * 8;
    const int segHi  = (lane >> 4) & 1;

    uint32_t af[4][4], bf[2][4][4];
    auto ldsmA = [&](uint32_t aBase, int ks) {
        const int kseg = ks * 2 + segHi;
        #pragma unroll
        for (int mt = 0; mt < 4; mt++)
            ldsm4(af[mt], aBase + swzB(mw + mt * 16 + rowSel, kseg));
    };
    auto ldsmB = [&](uint32_t bBase, int ks, int buf) {
        const int kseg = ks * 2 + segHi;
        #pragma unroll
        for (int nt = 0; nt < 4; nt++)
            ldsm4(bf[buf][nt], bBase + swzB(nw + nt * 16 + rowSel, kseg));
    };
    auto mma_step = [&](int buf) {
        #pragma unroll
        for (int mt = 0; mt < 4; mt++) {
            #pragma unroll
            for (int nt = 0; nt < 4; nt++) {
                mma_h(acc[mt][2 * nt],     af[mt], bf[buf][nt][0], bf[buf][nt][2]);
                mma_h(acc[mt][2 * nt + 1], af[mt], bf[buf][nt][1], bf[buf][nt][3]);
            }
        }
    };

    #pragma unroll 1
    for (int c = 0; c < NCHNK; c++) {
        // B(c)/A(c) resident; barrier also guarantees all reads of stage (c+1)&1 done.
        CP_WAIT(0);
        __syncthreads();
        if (c + 1 < NCHNK) load_stage(c + 1, (c + 1) & 1);

        const uint32_t aBase = sb + (uint32_t)(c & 1) * STAGEB;
        const uint32_t bBase = aBase + ASZ;

        ldsmA(aBase, 0);
        ldsmB(bBase, 0, 0);
        #pragma unroll
        for (int ks = 0; ks < 4; ks++) {
            const int cur = ks & 1;
            if (ks < 3) ldsmB(bBase, ks + 1, cur ^ 1);   // B(ks+1) hidden under mma(ks)
            mma_step(cur);
            if (ks < 3) ldsmA(aBase, ks + 1);            // A(ks+1) after af consumers
        }
    }

    // ---- epilogue: two 128-col halves staged through smem (R4-proven) ----
    float* tile = reinterpret_cast<float*>(smem);
    __syncthreads();
    const int dr = lane >> 2;
    const int dc = (lane & 3) * 2;
    const int myhalf = (wid & 3) >> 1;          // warp cols 0,1 -> half0; 2,3 -> half1
    const int nlb = (wid & 1) * 64;             // col base within the half

    #pragma unroll
    for (int h = 0; h < 2; h++) {
        if (myhalf == h) {
            #pragma unroll
            for (int mt = 0; mt < 4; mt++) {
                #pragma unroll
                for (int nt = 0; nt < 8; nt++) {
                    int r = mw + mt * 16 + dr;
                    int c2 = nlb + nt * 8 + dc;
                    float2 lo = __half22float2(*reinterpret_cast<__half2*>(&acc[mt][nt][0]));
                    float2 hi = __half22float2(*reinterpret_cast<__half2*>(&acc[mt][nt][1]));
                    tile[r * TPITCH + c2]           = lo.x;
                    tile[r * TPITCH + c2 + 1]       = lo.y;
                    tile[(r + 8) * TPITCH + c2]     = hi.x;
                    tile[(r + 8) * TPITCH + c2 + 1] = hi.y;
                }
            }
        }
        __syncthreads();

        #pragma unroll 4
        for (int g = 0; g < 16; g++) {
            const int nl = wid + 8 * g;          // 0..127
            const int p = h * 128 + nl;
            const int n = n0 + p;
            const float al = alphaS[p], be = betaS[p];
            const float sl = slopeS[p], sh = shiftS[p], pb = pbiasS[p];
            #pragma unroll
            for (int j = 0; j < 4; j++) {
                int ml = lane + 32 * j;
                int m = m0 + ml;
                int b = m / HWS;
                int hw = m - b * HWS;
                size_t gi = ((size_t)(b * CC + n)) * HWS + hw;
                float raw = tile[ml * TPITCH + nl];
                float sv = fmaf(al, raw, be) + x[gi];
                float t = sv - sh;
                out[gi] = ((t > 0.f) ? t : sl * t) + pb;
            }
        }
        __syncthreads();
    }
}

// ---------------- launch ----------------
extern "C" void kernel_launch(void* const* d_in, const int* in_sizes, int n_in,
                              void* d_out, int out_size) {
    const float* x   = (const float*)d_in[0];
    const float* rb  = (const float*)d_in[1];
    const float* W   = (const float*)d_in[2];
    const float* gam = (const float*)d_in[3];
    const float* bet = (const float*)d_in[4];
    const float* mea = (const float*)d_in[5];
    const float* var = (const float*)d_in[6];
    const float* slo = (const float*)d_in[7];
    const float* shi = (const float*)d_in[8];
    const float* pbi = (const float*)d_in[9];
    float* out = (float*)d_out;

    cudaFuncSetAttribute(gemm_kernel, cudaFuncAttributeMaxDynamicSharedMemorySize, SMTOTAL);

    pre_kernel<<<64 + 13 * 8 * 64, 256>>>(W, gam, bet, mea, var, x, rb);
    gemm_kernel<<<dim3(2, MTOT / MTILE), 256, SMTOTAL>>>(x, slo, shi, pbi, out);
}